// round 15
// baseline (speedup 1.0000x reference)
#include <cuda_runtime.h>
#include <cuda_bf16.h>
#include <cstdint>

// ---------------------------------------------------------------------------
// TimemixingFC_channel, round 15: ONE kernel launch, zero prep, generation-
// counter sync (no flag resets -> no prep launch needed).
//   Algebra: per branch qkv = x@W^T + b; S=2 attention -> 2x2 G per
//   (position, window) group; o = q@G; proj. Branch-0 proj folded into
//   branch-1 qkv (W' = Wsw@Wp, b' = Wsw@bp + bsw). Rolls folded into pairing.
//   Grid 291 = 256 work + 18 W'-fold + 1 b' + 4 projs-tr + 12 lr-tr blocks,
//   all resident in wave 1 (<=296 slots) -> deadlock-free.
//   Generation counters: g_flag[bid]/g_tr/g_fold increment once per launch,
//   never reset. Work block reads its own flag (sole writer) = generation N;
//   phase A stages A-tile from x (weight-independent) while lr-transpose
//   side blocks run, spins g_tr >= 12(N+1), stages weights, computes; sets
//   flag = N+1; phase B gates on g_fold >= 23(N+1) and neighbor flag > N.
// ---------------------------------------------------------------------------

#define SMEM_BYTES 91648

static __device__ __align__(16) __nv_bfloat16 g_mid[32768 * 96];   // o0 (bf16)
static __device__ __align__(16) __nv_bfloat16 g_wbf[2][288 * 104]; // qkv W, [jf][c] pad104
static __device__ __align__(16) __nv_bfloat16 g_wpbf[96 * 104];    // projs_w
static __device__ float g_b1[288];                                 // b' fold bias
static __device__ int   g_flag[256];                               // generation per work block
static __device__ int   g_tr;                                      // lr-transpose counter
static __device__ int   g_fold;                                    // fold/b'/projs counter

// ---- PTX helpers (valid under compute_100) --------------------------------
__device__ __forceinline__ uint32_t smem_u32(const void* p) {
    uint32_t a;
    asm("{ .reg .u64 t; cvta.to.shared.u64 t, %1; cvt.u32.u64 %0, t; }" : "=r"(a) : "l"(p));
    return a;
}
#define CPA16(dst, src) \
    asm volatile("cp.async.cg.shared.global [%0], [%1], 16;" :: "r"(dst), "l"(src) : "memory")
#define CPA_COMMIT() asm volatile("cp.async.commit_group;" ::: "memory")
#define CPA_WAIT(n)  asm volatile("cp.async.wait_group %0;" :: "n"(n) : "memory")

__device__ __forceinline__ void ldsm4(uint32_t& r0, uint32_t& r1, uint32_t& r2,
                                      uint32_t& r3, uint32_t addr) {
    asm volatile("ldmatrix.sync.aligned.m8n8.x4.shared.b16 {%0,%1,%2,%3}, [%4];"
                 : "=r"(r0), "=r"(r1), "=r"(r2), "=r"(r3) : "r"(addr));
}
#define MMA(acc, a, b0, b1) \
    asm volatile("mma.sync.aligned.m16n8k16.row.col.f32.bf16.bf16.f32 " \
        "{%0,%1,%2,%3}, {%4,%5,%6,%7}, {%8,%9}, {%0,%1,%2,%3};" \
        : "+f"((acc)[0]), "+f"((acc)[1]), "+f"((acc)[2]), "+f"((acc)[3]) \
        : "r"((a)[0]), "r"((a)[1]), "r"((a)[2]), "r"((a)[3]), "r"(b0), "r"(b1))

// ---------------------------------------------------------------------------
// One n-tile pair (tiles 2p, 2p+1): D[16x16] over K=96, cached A fragments.
// ---------------------------------------------------------------------------
__device__ __forceinline__ void hmma_pair(const uint32_t af[6][4], uint32_t wAddr,
                                          int p, float acc[2][4])
{
#pragma unroll
    for (int t = 0; t < 2; t++)
#pragma unroll
        for (int r = 0; r < 4; r++) acc[t][r] = 0.f;
#pragma unroll
    for (int ks = 0; ks < 6; ks++) {
        uint32_t b0, b1, b2, b3;
        ldsm4(b0, b1, b2, b3, wAddr + p * 3328 + ks * 32);
        MMA(acc[0], af[ks], b0, b2);
        MMA(acc[1], af[ks], b1, b3);
    }
}

// stage one 96x104-bf16 weight image (19968B = 1248 x 16B) via cp.async
__device__ __forceinline__ void stage_w_async(uint32_t dst, const char* src, int tid)
{
    for (int f = tid; f < 1248; f += 256)
        CPA16(dst + f * 16, src + f * 16);
}

// ---------------------------------------------------------------------------
// Side blocks (bid >= 256):
//   256..273: W' fold (16 rows each)      -> g_fold++
//   274:      b'                          -> g_fold++
//   275..278: projs_w transpose (2304 ea) -> g_fold++
//   279..290: lr_w transpose (2304 ea)    -> g_tr++
// ---------------------------------------------------------------------------
__device__ void side_block(char* smem, int bid, int tid,
                           const float* lr, const float* pr,
                           const float* sw, const float* swb,
                           const float* prb, const float* prs_ext)
{
    float* prs  = (float*)smem;             // [96][100] fp32
    float* sws  = (float*)(smem + 38400);   // [16][96] fp32
    float* prbs = (float*)(smem + 44544);   // [96]
    int* ctr = &g_fold;

    if (bid < 274) {
        // ---- 16 rows of W' = sw @ pr ----
        int jf0 = (bid - 256) * 16;
        for (int i = tid; i < 2304; i += 256) {
            int t = i / 24, c4 = (i % 24) * 4;
            *(float4*)&prs[t * 100 + c4] = *(const float4*)&pr[t * 96 + c4];
        }
        for (int i = tid; i < 1536; i += 256)
            sws[i] = sw[jf0 * 96 + i];
        __syncthreads();

        int rgrp = tid >> 4, cgrp = tid & 15;
        int c0 = cgrp * 6;
        const float* swr = &sws[rgrp * 96];
        float acc[6];
#pragma unroll
        for (int j = 0; j < 6; j++) acc[j] = 0.f;
#pragma unroll 4
        for (int t = 0; t < 96; t++) {
            float s = swr[t];
#pragma unroll
            for (int j = 0; j < 6; j++)
                acc[j] = fmaf(s, prs[t * 100 + c0 + j], acc[j]);
        }
        int jf = jf0 + rgrp;
#pragma unroll
        for (int j = 0; j < 6; j++)
            g_wbf[1][jf * 104 + c0 + j] = __float2bfloat16(acc[j]);
    } else if (bid == 274) {
        // ---- b' = sw @ prb + swb ----
        if (tid < 96) prbs[tid] = prb[tid];
        __syncthreads();
        int rgrp = tid >> 4, cgrp = tid & 15;
        int c0 = cgrp * 6;
        for (int r = rgrp; r < 288; r += 16) {
            const float* swr = sw + r * 96;
            float pacc = 0.f;
#pragma unroll
            for (int t = 0; t < 6; t++)
                pacc = fmaf(swr[c0 + t], prbs[c0 + t], pacc);
#pragma unroll
            for (int off = 1; off < 16; off <<= 1)
                pacc += __shfl_xor_sync(0xffffffffu, pacc, off);
            if (cgrp == 0) g_b1[r] = pacc + swb[r];
        }
    } else if (bid < 279) {
        // ---- projs_w transpose: 4 blocks x 2304 elems ----
        int base = (bid - 275) * 2304;
#pragma unroll
        for (int k = 0; k < 9; k++) {
            int idx = base + k * 256 + tid;   // < 9216
            int j = idx / 96, c = idx % 96;
            g_wpbf[j * 104 + c] = __float2bfloat16(prs_ext[idx]);
        }
    } else {
        // ---- lr_w transpose: 12 blocks x 2304 elems ----
        int base = (bid - 279) * 2304;
#pragma unroll
        for (int k = 0; k < 9; k++) {
            int idx = base + k * 256 + tid;   // < 27648
            int jf = idx / 96, c = idx % 96;
            g_wbf[0][jf * 104 + c] = __float2bfloat16(lr[idx]);
        }
        ctr = &g_tr;
    }
    __threadfence();
    __syncthreads();
    if (tid == 0) atomicAdd(ctr, 1);
}

// ---------------------------------------------------------------------------
// One branch phase. BR=0: x -> o0 (g_mid), gated on g_tr inside (f0 gen).
// BR=1: o0 -> out (gates done by caller).
// ---------------------------------------------------------------------------
template <int BR>
__device__ __forceinline__ void run_phase(char* smem, uint32_t sb,
                                          const float* __restrict__ xin_ext,
                                          const float* __restrict__ QB,
                                          const float* __restrict__ pr_b,
                                          float* __restrict__ out_ext,
                                          int shift, int bid, int f0)
{
    int*   tb = (int*)smem;
    float* qb = (float*)(smem + 512);
    float* pb = (float*)(smem + 1664);
    float* gt = (float*)(smem + 2048);
    float* gc = (float*)(smem + 4096);
    char*  smA = smem + 5120;
    uint32_t smAu = sb + 5120;
    uint32_t smWu = sb + 31744;             // 3 x [96][104] bf16 slots

    int tid = threadIdx.x, w = tid >> 5, lane = tid & 31;
    int g = lane >> 2, tig = lane & 3;
    int l16 = lane & 15, lh = lane >> 4;
    int row0 = w * 16;

    if (BR && tid < 96) pb[tid] = pr_b[tid];

    if (tid < 128) {
        int pi = tid & 63;
        int gg = (bid << 6) + pi;
        int b = gg >> 13, dw = (gg >> 10) & 7, p = gg & 1023;
        int d = (2 * dw + (tid >> 6) + shift) & 15;
        tb[tid] = ((b * 16 + d) * 1024 + p) * 96;
    }

    const char* WB = (const char*)g_wbf[BR];

    if (BR == 0) {
        __syncthreads();   // tb ready
        // A tile from x first (weight-independent; overlaps lr transpose)
        for (int f4 = tid; f4 < 3072; f4 += 256) {
            int l = f4 / 24, q4 = f4 % 24;
            float4 v = *(const float4*)&xin_ext[tb[l] + q4 * 4];
            __nv_bfloat162 p0 = __floats2bfloat162_rn(v.x, v.y);
            __nv_bfloat162 p1 = __floats2bfloat162_rn(v.z, v.w);
            *(uint2*)(smA + l * 208 + q4 * 8) =
                make_uint2(*(uint32_t*)&p0, *(uint32_t*)&p1);
        }
        for (int i = tid; i < 288; i += 256) qb[i] = QB[i];
        // gate: lr transpose done (12 side blocks, generation f0+1)
        if (tid == 0)
            while (*(volatile int*)&g_tr < 12 * (f0 + 1)) {}
        __syncthreads();
        __threadfence();
        stage_w_async(smWu,             WB + 96 * 208, tid);   // K
        stage_w_async(smWu + 19968,     WB + 192 * 208, tid);  // V
        stage_w_async(smWu + 2 * 19968, WB,             tid);  // Q
        CPA_COMMIT();
    } else {
        for (int i = tid; i < 288; i += 256) qb[i] = QB[i];
        __syncthreads();   // tb ready
        for (int f = tid; f < 1536; f += 256) {       // A tile via cp.async (L2)
            int l = f / 12, u = f % 12;
            CPA16(smAu + l * 208 + u * 16,
                  (const char*)g_mid + (size_t)tb[l] * 2 + u * 16);
        }
        stage_w_async(smWu,             WB + 96 * 208, tid);   // K'
        stage_w_async(smWu + 19968,     WB + 192 * 208, tid);  // V'
        stage_w_async(smWu + 2 * 19968, WB,             tid);  // Q'
        CPA_COMMIT();
    }

    uint32_t aAddr = smAu + ((row0 + l16) * 104 + lh * 8) * 2;
    uint32_t wAddr = smWu + (l16 * 104 + lh * 8) * 2;

    CPA_WAIT(0);
    __syncthreads();        // A + K + V + Q visible

    uint32_t af[6][4];
#pragma unroll
    for (int ks = 0; ks < 6; ks++)
        ldsm4(af[ks][0], af[ks][1], af[ks][2], af[ks][3], aAddr + ks * 32);

    // ---- mega loop: K, V, Q per pair; K/V fold into G; Q held in regs ----
    float G[8];
    float qacc[6][2][4];
#pragma unroll
    for (int i = 0; i < 8; i++) G[i] = 0.f;
#pragma unroll
    for (int p = 0; p < 6; p++) {
        float ka[2][4], va[2][4];
        hmma_pair(af, wAddr,             p, ka);
        hmma_pair(af, wAddr + 19968,     p, va);
        hmma_pair(af, wAddr + 2 * 19968, p, qacc[p]);
#pragma unroll
        for (int t = 0; t < 2; t++) {
            int j0 = (2 * p + t) * 8 + tig * 2;
            float kb0 = qb[96 + j0], kb1 = qb[96 + j0 + 1];
            float vb0 = qb[192 + j0], vb1 = qb[192 + j0 + 1];
            float k0 = ka[t][0] + kb0, k1 = ka[t][1] + kb1;
            float k2 = ka[t][2] + kb0, k3 = ka[t][3] + kb1;
            float v0 = va[t][0] + vb0, v1 = va[t][1] + vb1;
            float v2 = va[t][2] + vb0, v3 = va[t][3] + vb1;
            G[0] = fmaf(k0, v0, G[0]); G[1] = fmaf(k0, v1, G[1]);
            G[2] = fmaf(k1, v0, G[2]); G[3] = fmaf(k1, v1, G[3]);
            G[4] = fmaf(k2, v2, G[4]); G[5] = fmaf(k2, v3, G[5]);
            G[6] = fmaf(k3, v2, G[6]); G[7] = fmaf(k3, v3, G[7]);
        }
    }
    __syncthreads();        // all warps done reading weight slots

    if (BR) { stage_w_async(smWu, (const char*)g_wpbf, tid); CPA_COMMIT(); }

#pragma unroll
    for (int off = 1; off <= 2; off <<= 1)
#pragma unroll
        for (int i = 0; i < 8; i++)
            G[i] += __shfl_xor_sync(0xffffffffu, G[i], off);
    if (tig == 0) {
        *(float4*)&gt[(row0 + g) * 4]     = make_float4(G[0], G[1], G[2], G[3]);
        *(float4*)&gt[(row0 + g + 8) * 4] = make_float4(G[4], G[5], G[6], G[7]);
    }
    __syncthreads();
    if (tid < 64) {
        float4 a = *(float4*)&gt[tid * 4];
        float4 b4 = *(float4*)&gt[(tid + 64) * 4];
        *(float4*)&gc[tid * 4] =
            make_float4(a.x + b4.x, a.y + b4.y, a.z + b4.z, a.w + b4.w);
    }
    CPA_WAIT(0);
    __syncthreads();        // gc (+ proj weights) visible

    float4 Glo = *(float4*)&gc[((row0 + g) & 63) * 4];
    float4 Ghi = *(float4*)&gc[((row0 + g + 8) & 63) * 4];

#pragma unroll
    for (int p = 0; p < 6; p++) {
#pragma unroll
        for (int t = 0; t < 2; t++) {
            int j0 = (2 * p + t) * 8 + tig * 2;
            float b0 = qb[j0], b1 = qb[j0 + 1];
            float q0 = qacc[p][t][0] + b0, q1 = qacc[p][t][1] + b1;
            float q2 = qacc[p][t][2] + b0, q3 = qacc[p][t][3] + b1;
            float o0 = q0 * Glo.x + q1 * Glo.z;
            float o1 = q0 * Glo.y + q1 * Glo.w;
            float o2 = q2 * Ghi.x + q3 * Ghi.z;
            float o3 = q2 * Ghi.y + q3 * Ghi.w;
            __nv_bfloat162 plo = __floats2bfloat162_rn(o0, o1);
            __nv_bfloat162 phi = __floats2bfloat162_rn(o2, o3);
            *(uint32_t*)(smA + (row0 + g) * 208 + j0 * 2)     = *(uint32_t*)&plo;
            *(uint32_t*)(smA + (row0 + g + 8) * 208 + j0 * 2) = *(uint32_t*)&phi;
        }
    }

    if (BR == 0) {
        __syncthreads();
        for (int f = tid; f < 1536; f += 256) {
            int l = f / 12, u = f % 12;
            *(uint4*)((char*)g_mid + (size_t)tb[l] * 2 + u * 16) =
                *(const uint4*)(smA + l * 208 + u * 16);
        }
    } else {
        __syncwarp();       // order own-warp STS -> LDSM
        uint32_t of[6][4];
#pragma unroll
        for (int ks = 0; ks < 6; ks++)
            ldsm4(of[ks][0], of[ks][1], of[ks][2], of[ks][3], aAddr + ks * 32);
        int tbg = tb[row0 + g], tbh = tb[row0 + g + 8];
#pragma unroll
        for (int p = 0; p < 6; p++) {
            float pa[2][4];
            hmma_pair(of, wAddr, p, pa);     // slot0 = proj weights
#pragma unroll
            for (int t = 0; t < 2; t++) {
                int j0 = (2 * p + t) * 8 + tig * 2;
                float b0 = pb[j0], b1 = pb[j0 + 1];
                *(float2*)&out_ext[tbg + j0] =
                    make_float2(pa[t][0] + b0, pa[t][1] + b1);
                *(float2*)&out_ext[tbh + j0] =
                    make_float2(pa[t][2] + b0, pa[t][3] + b1);
            }
        }
    }
}

// ---------------------------------------------------------------------------
// Mega kernel. Grid 291 x 256 (256 work + 35 side), all resident in wave 1.
// ---------------------------------------------------------------------------
__global__ void __launch_bounds__(256, 2)
fused_mega(const float* __restrict__ x,
           const float* __restrict__ lr_w,
           const float* __restrict__ lr_b,
           const float* __restrict__ projs_b,
           float* __restrict__ out,
           const float* __restrict__ f_pr,    // proj_w
           const float* __restrict__ f_sw,    // sw_w
           const float* __restrict__ f_swb,   // sw_b
           const float* __restrict__ f_prb,   // proj_b
           const float* __restrict__ f_prs)   // projs_w
{
    extern __shared__ char smem[];
    int tid = threadIdx.x, bid = blockIdx.x;

    if (bid >= 256) {
        side_block(smem, bid, tid, lr_w, f_pr, f_sw, f_swb, f_prb, f_prs);
        return;
    }

    uint32_t sb = smem_u32(smem);

    // generation number = own flag value (sole writer is this block)
    int f0 = 0;
    if (tid == 0) f0 = *(volatile int*)&g_flag[bid];

    // ---- phase A: branch 0, pairs (2w, 2w+1), x -> o0 ----
    run_phase<0>(smem, sb, x, lr_b, nullptr, nullptr, 0, bid, f0);

    __threadfence();
    __syncthreads();
    if (tid == 0) atomicExch(&g_flag[bid], f0 + 1);

    // ---- wait: dw-1 neighbor's phase A + all fold/transpose side blocks ----
    if (tid == 0) {
        int dw = (bid >> 4) & 7;
        int dep = (bid & 0x8F) | (((dw + 7) & 7) << 4);
        while (*(volatile int*)&g_fold < 23 * (f0 + 1)) {}
        while (*(volatile int*)&g_flag[dep] <= f0) {}
    }
    __syncthreads();
    __threadfence();

    // ---- phase B: branch 1, pairs (2w-1, 2w), o0 -> out ----
    run_phase<1>(smem, sb, nullptr, g_b1, projs_b, out, 15, bid, f0);
}

// ---------------------------------------------------------------------------
extern "C" void kernel_launch(void* const* d_in, const int* in_sizes, int n_in,
                              void* d_out, int out_size)
{
    const float* x       = (const float*)d_in[0];
    const float* lr_w    = (const float*)d_in[1];
    const float* lr_b    = (const float*)d_in[2];
    const float* proj_w  = (const float*)d_in[3];
    const float* proj_b  = (const float*)d_in[4];
    const float* sw_w    = (const float*)d_in[5];
    const float* sw_b    = (const float*)d_in[6];
    const float* projs_w = (const float*)d_in[7];
    const float* projs_b = (const float*)d_in[8];
    float* out = (float*)d_out;

    cudaFuncSetAttribute(fused_mega,
                         cudaFuncAttributeMaxDynamicSharedMemorySize, SMEM_BYTES);

    fused_mega<<<291, 256, SMEM_BYTES>>>(x, lr_w, lr_b, projs_b, out,
                                         proj_w, sw_w, sw_b, proj_b, projs_w);
}